// round 17
// baseline (speedup 1.0000x reference)
#include <cuda_runtime.h>
#include <cuda_fp16.h>

#define PI_D 3.14159265358979323846
#define NN   512
#define N2   262144
#define NIMG 144
#define GSIZE 12          // images per pipeline group (7-slice window ~84MB fits L2)
#define NG    12          // number of groups
#define BPS   (GSIZE*64)  // blocks per pass-slice = 768
#define RSTRIDE 584       // row kernels (half2 units): warp-private region
#define CSTRIDE 580       // col kernels (half2 units): (2p*580)%32=8p -> conflict-free
#define SOFF   4672       // second exchange buffer offset (half2 units; 4672%32==0)
#define TWSZ   584        // skewed twiddle table (float2, max SK(511)=574)
#define SK(i) ((i) + ((i)>>3))

typedef unsigned long long cplx;   // packed complex: lo=re, hi=im (f32x2 register pair)

// ---------------- device scratch (no allocations allowed) ----------------
static __device__ __half2 d_field[(size_t)NIMG*N2]; // ~151 MB, fp16 inter-pass field
static __device__ float2 d_Tl[3*N2];                 // layer transmissions
static __device__ float2 d_Hb[N2];                   // H / N^2
static __device__ float2 d_Hb2[N2];                  // H^2 / N^2
static __device__ float2 d_tw[NN];                   // e^{-2pi i k/512}
static __device__ unsigned char d_cls[N2];           // pixel -> class (255 = none)
static __device__ float d_part[NIMG*64*10];          // per-block class partials

// ---------------- packed-complex helpers ----------------
__device__ __forceinline__ cplx mkc(float x, float y){
    cplx r; asm("mov.b64 %0, {%1, %2};" : "=l"(r) : "f"(x), "f"(y)); return r;
}
__device__ __forceinline__ float2 c2f(cplx a){
    float2 f; asm("mov.b64 {%0, %1}, %2;" : "=f"(f.x), "=f"(f.y) : "l"(a)); return f;
}
__device__ __forceinline__ cplx cadd(cplx a, cplx b){
    cplx r; asm("add.rn.f32x2 %0, %1, %2;" : "=l"(r) : "l"(a), "l"(b)); return r;
}
__device__ __forceinline__ cplx csub(cplx a, cplx b){
    cplx r; asm("sub.rn.f32x2 %0, %1, %2;" : "=l"(r) : "l"(a), "l"(b)); return r;
}
// complex * complex (b as float2), scalar datapath
__device__ __forceinline__ cplx cmulf(cplx a, float2 b){
    float2 f = c2f(a);
    return mkc(f.x*b.x - f.y*b.y, f.x*b.y + f.y*b.x);
}
// complex * conj(b)
__device__ __forceinline__ cplx cmulcf(cplx a, float2 b){
    float2 f = c2f(a);
    return mkc(f.x*b.x + f.y*b.y, f.y*b.x - f.x*b.y);
}
__device__ __forceinline__ __half2 c2h(cplx a){
    float2 f = c2f(a); return __float22half2_rn(f);
}
__device__ __forceinline__ cplx h2c(__half2 h){
    float2 f = __half22float2(h); return mkc(f.x, f.y);
}
// bit reinterpretation uint32 <-> half2
__device__ __forceinline__ __half2 u2h(unsigned int u){
    union { unsigned int u; __half2 h; } c; c.u = u; return c.h;
}
__device__ __forceinline__ unsigned int h2u(__half2 h){
    union { unsigned int u; __half2 h; } c; c.h = h; return c.u;
}

#define BREV_DECL const int brev[8] = {0,4,2,6,1,5,3,7}

// ---------------- radix-8 butterfly (DIF, output bit-reversed) ----------------
template<bool INV>
__device__ __forceinline__ void fft8(cplx v[8]){
    const float C0 = 0.70710678118654752440f;
#define BTF(a,b) { cplx s_ = cadd(a,b); b = csub(a,b); a = s_; }
    BTF(v[0],v[4]); BTF(v[1],v[5]); BTF(v[2],v[6]); BTF(v[3],v[7]);
    {   // v5 *= (C0, -+C0); v6 *= -+i; v7 *= (-C0, -+C0)
        float2 f5 = c2f(v[5]), f6 = c2f(v[6]), f7 = c2f(v[7]);
        if (INV){
            v[5] = mkc(C0*(f5.x - f5.y), C0*(f5.x + f5.y));
            v[6] = mkc(-f6.y, f6.x);
            v[7] = mkc(-C0*(f7.x + f7.y), C0*(f7.x - f7.y));
        } else {
            v[5] = mkc(C0*(f5.x + f5.y), C0*(f5.y - f5.x));
            v[6] = mkc(f6.y, -f6.x);
            v[7] = mkc(C0*(f7.y - f7.x), -C0*(f7.x + f7.y));
        }
    }
    BTF(v[0],v[2]); BTF(v[1],v[3]); BTF(v[4],v[6]); BTF(v[5],v[7]);
    {
        float2 f3 = c2f(v[3]), f7 = c2f(v[7]);
        if (INV){ v[3] = mkc(-f3.y, f3.x); v[7] = mkc(-f7.y, f7.x); }
        else    { v[3] = mkc(f3.y, -f3.x); v[7] = mkc(f7.y, -f7.x); }
    }
    BTF(v[0],v[1]); BTF(v[2],v[3]); BTF(v[4],v[5]); BTF(v[6],v[7]);
#undef BTF
}

// apply brev permutation in registers (pure renaming)
__device__ __forceinline__ void permute_brev(cplx v[8]){
    BREV_DECL;
    cplx t[8];
#pragma unroll
    for (int r=0;r<8;r++) t[r] = v[brev[r]];
#pragma unroll
    for (int r=0;r<8;r++) v[r] = t[r];
}

// twiddle apply: forward = cmul, inverse = conj-mul
template<bool INV>
__device__ __forceinline__ cplx twmul(cplx a, float2 q){
    return INV ? cmulcf(a, q) : cmulf(a, q);
}

// NOTE: tw[] is float2, stored SKEWED: tw[k] lives at tw[SK(k)].
// Exchanges are DOUBLE-BUFFERED (s0 for stage0, s1 for stage1): no WAR syncs,
// no inter-FFT sync. Row FFT regions are warp-private -> __syncwarp only.

// ---- dual-slot 512-pt FFT, ONE line (warp-private), thread owns slots j, j+32
template<bool INV, bool PERM>
__device__ __forceinline__ void fft512_dual(cplx v[8], cplx w[8],
                                            __half2* s0, __half2* s1,
                                            int j, const float2* tw){
    BREV_DECL;
    if (PERM){ permute_brev(v); permute_brev(w); }
    fft8<INV>(v);
#pragma unroll
    for (int r=0;r<8;r++) s0[SK(8*j+r)] = c2h(v[brev[r]]);
    fft8<INV>(w);
#pragma unroll
    for (int r=0;r<8;r++) s0[SK(8*(j+32)+r)] = c2h(w[brev[r]]);
    __syncwarp();
#pragma unroll
    for (int r=0;r<8;r++){ v[r] = h2c(s0[SK(j+64*r)]); w[r] = h2c(s0[SK(j+32+64*r)]); }
    int jm = j & 7;
#pragma unroll
    for (int r=1;r<8;r++){
        float2 q = tw[SK(r*jm*8)];
        v[r] = twmul<INV>(v[r], q); w[r] = twmul<INV>(w[r], q);  // (j+32)&7 == j&7
    }
    int iv = ((j - jm) << 3) + jm;
    fft8<INV>(v);
#pragma unroll
    for (int r=0;r<8;r++) s1[SK(iv + 8*r)] = c2h(v[brev[r]]);
    fft8<INV>(w);
#pragma unroll
    for (int r=0;r<8;r++) s1[SK(iv + 256 + 8*r)] = c2h(w[brev[r]]);
    __syncwarp();
#pragma unroll
    for (int r=0;r<8;r++){ v[r] = h2c(s1[SK(j+64*r)]); w[r] = h2c(s1[SK(j+32+64*r)]); }
#pragma unroll
    for (int r=1;r<8;r++){
        v[r] = twmul<INV>(v[r], tw[SK(r*j)]);
        w[r] = twmul<INV>(w[r], tw[SK(r*(j+32))]);
    }
    fft8<INV>(v); fft8<INV>(w);
}

// ---- dual-line 512-pt FFT: TWO independent lines, regions span warps ->
// block syncs, but only 2 per FFT (double-buffered, no WAR syncs).
template<bool INV, bool PERM>
__device__ __forceinline__ void fft512_dual2(cplx v[8], cplx w[8],
                                             __half2* sA0, __half2* sB0,
                                             __half2* sA1, __half2* sB1,
                                             int j, const float2* tw){
    BREV_DECL;
    if (PERM){ permute_brev(v); permute_brev(w); }
    fft8<INV>(v);
#pragma unroll
    for (int r=0;r<8;r++) sA0[SK(8*j+r)] = c2h(v[brev[r]]);
    fft8<INV>(w);
#pragma unroll
    for (int r=0;r<8;r++) sB0[SK(8*j+r)] = c2h(w[brev[r]]);
    __syncthreads();
#pragma unroll
    for (int r=0;r<8;r++){ v[r] = h2c(sA0[SK(j+64*r)]); w[r] = h2c(sB0[SK(j+64*r)]); }
    int jm = j & 7;
#pragma unroll
    for (int r=1;r<8;r++){
        float2 q = tw[SK(r*jm*8)];
        v[r] = twmul<INV>(v[r], q); w[r] = twmul<INV>(w[r], q);
    }
    int idxD = ((j - jm) << 3) + jm;
    fft8<INV>(v);
#pragma unroll
    for (int r=0;r<8;r++) sA1[SK(idxD + 8*r)] = c2h(v[brev[r]]);
    fft8<INV>(w);
#pragma unroll
    for (int r=0;r<8;r++) sB1[SK(idxD + 8*r)] = c2h(w[brev[r]]);
    __syncthreads();
#pragma unroll
    for (int r=0;r<8;r++){ v[r] = h2c(sA1[SK(j+64*r)]); w[r] = h2c(sB1[SK(j+64*r)]); }
#pragma unroll
    for (int r=1;r<8;r++){
        float2 q = tw[SK(r*j)];
        v[r] = twmul<INV>(v[r], q); w[r] = twmul<INV>(w[r], q);
    }
    fft8<INV>(v); fft8<INV>(w);
}

// ---------------- init kernel (twiddles folded into block 0) ----------------
__global__ void k_init(const float* __restrict__ amp, const float* __restrict__ phs,
                       const float* __restrict__ mask){
    int i = blockIdx.x, j = threadIdx.x;
    int idx = i*NN + j;
    if (i == 0){
        double ang = -2.0*PI_D*(double)j/512.0;
        d_tw[j] = make_float2((float)cos(ang), (float)sin(ang));
    }
    float inv = 1.0f/(512.0f*8e-6f);
    float fx = (float)(i<256 ? i : i-512) * inv;
    float fy = (float)(j<256 ? j : j-512) * inv;
    const float lam = 5.32e-7f;
    float lx = lam*fx, ly = lam*fy;
    float arg = 1.0f - lx*lx - ly*ly;
    float sa = sqrtf(fmaxf(arg, 0.0f));
    const float KZ = (float)(2.0*PI_D/5.32e-7*0.05);
    float phi = KZ * sa;                   // f32 rounding, matches jax path
    double s, c;
    sincos((double)phi, &s, &c);           // accurate for huge args
    float hr = (float)c, hi = (float)s;
    const float sc = 1.0f/262144.0f;
    d_Hb [idx] = make_float2(hr*sc, hi*sc);
    d_Hb2[idx] = make_float2((hr*hr - hi*hi)*sc, 2.0f*hr*hi*sc);
#pragma unroll
    for (int l=0;l<3;l++){
        float a = amp[l*N2+idx], p = phs[l*N2+idx];
        float sn, cs; sincosf(p, &sn, &cs);
        d_Tl[l*N2+idx] = make_float2(a*cs, a*sn);
    }
    unsigned char cl = 255;
#pragma unroll
    for (int q=0;q<10;q++) if (mask[q*N2 + idx] > 0.5f) cl = (unsigned char)q;
    d_cls[idx] = cl;
}

// ---------------- pass bodies (device functions) ----------------

__device__ __forceinline__ void body_p1(__half2* S, float2* TW,
                                        const float* __restrict__ xamp,
                                        const float* __restrict__ pn,
                                        int inner, int img0){
    int t = threadIdx.x;
    int line = t >> 5, j = t & 31;
    int img  = img0 + (inner >> 6);
    int row  = ((inner & 63) << 3) + line;
    int b = img & 15, m = img >> 4;
    float fm = 0.5f * (float)(m+1);
    size_t ibase = (size_t)img*N2 + (size_t)row*NN;
    size_t bbase = (size_t)b  *N2 + (size_t)row*NN;
    cplx v[8], w[8];
#pragma unroll
    for (int r=0;r<8;r++){
        int e1 = j + 64*r, e2 = j + 32 + 64*r;
        float p1v = pn[ibase + e1], p2v = pn[ibase + e2];
        float x1 = xamp[bbase + e1], x2 = xamp[bbase + e2];
        float sn, cs;
        __sincosf(p1v*fm, &sn, &cs);
        v[r] = cmulf(mkc(x1*cs, x1*sn), d_Tl[row*NN + e1]);
        __sincosf(p2v*fm, &sn, &cs);
        w[r] = cmulf(mkc(x2*cs, x2*sn), d_Tl[row*NN + e2]);
    }
    fft512_dual<false,false>(v, w, S + line*RSTRIDE, S + SOFF + line*RSTRIDE, j, TW);
    BREV_DECL;
#pragma unroll
    for (int r=0;r<8;r++){
        d_field[ibase + j + 64*r]      = c2h(v[brev[r]]);
        d_field[ibase + j + 32 + 64*r] = c2h(w[brev[r]]);
    }
}

__device__ __forceinline__ void body_col(__half2* S, float2* TW,
                                         const float2* __restrict__ Hm,
                                         int inner, int img0){
    int t = threadIdx.x;
    int p = t & 3, j = t >> 2;          // pair id, slot
    int img = img0 + (inner >> 6);
    int colA = ((inner & 63) << 3) + 2*p;
    size_t ibase = (size_t)img*N2;
    BREV_DECL;
    cplx v[8], w[8];
#pragma unroll
    for (int r=0;r<8;r++){
        uint2 U = *(const uint2*)&d_field[ibase + (size_t)(j+64*r)*NN + colA];
        v[r] = h2c(u2h(U.x));
        w[r] = h2c(u2h(U.y));
    }
    __half2* sA0 = S + (2*p  )*CSTRIDE;
    __half2* sB0 = S + (2*p+1)*CSTRIDE;
    __half2* sA1 = sA0 + SOFF;
    __half2* sB1 = sB0 + SOFF;
    fft512_dual2<false,false>(v, w, sA0, sB0, sA1, sB1, j, TW);
    // in-place spectral multiply: v[i] holds elem j+64*brev[i]
#pragma unroll
    for (int i=0;i<8;i++){
        float4 Hp = *(const float4*)&Hm[(j+64*brev[i])*NN + colA];
        v[i] = cmulf(v[i], make_float2(Hp.x, Hp.y));
        w[i] = cmulf(w[i], make_float2(Hp.z, Hp.w));
    }
    // no sync needed: FFT2 stage0 writes buffer0, whose last reads preceded
    // FFT1's stage1 __syncthreads
    fft512_dual2<true,true>(v, w, sA0, sB0, sA1, sB1, j, TW);
#pragma unroll
    for (int r=0;r<8;r++){
        uint2 U;
        U.x = h2u(c2h(v[brev[r]]));
        U.y = h2u(c2h(w[brev[r]]));
        *(uint2*)&d_field[ibase + (size_t)(j+64*r)*NN + colA] = U;
    }
}

__device__ __forceinline__ void body_mid(__half2* S, float2* TW, int l,
                                         int inner, int img0){
    int t = threadIdx.x;
    int line = t >> 5, j = t & 31;
    int img  = img0 + (inner >> 6);
    int row  = ((inner & 63) << 3) + line;
    size_t ibase = (size_t)img*N2 + (size_t)row*NN;
    BREV_DECL;
    cplx v[8], w[8];
#pragma unroll
    for (int r=0;r<8;r++){
        v[r] = h2c(d_field[ibase + j + 64*r]);
        w[r] = h2c(d_field[ibase + j + 32 + 64*r]);
    }
    __half2* s0 = S + line*RSTRIDE;
    __half2* s1 = s0 + SOFF;
    fft512_dual<true,false>(v, w, s0, s1, j, TW);
    const float2* __restrict__ T = d_Tl + l*N2 + row*NN;
#pragma unroll
    for (int i=0;i<8;i++){
        v[i] = cmulf(v[i], T[j + 64*brev[i]]);
        w[i] = cmulf(w[i], T[j + 32 + 64*brev[i]]);
    }
    // no sync: FFT2 stage0 writes s0, last read before FFT1's stage1 syncwarp
    fft512_dual<false,true>(v, w, s0, s1, j, TW);
#pragma unroll
    for (int r=0;r<8;r++){
        d_field[ibase + j + 64*r]      = c2h(v[brev[r]]);
        d_field[ibase + j + 32 + 64*r] = c2h(w[brev[r]]);
    }
}

__device__ __forceinline__ void body_p7(__half2* S, float2* TW, float (*WP)[10],
                                        int inner, int img0){
    int t = threadIdx.x;
    int line = t >> 5, j = t & 31;
    int img  = img0 + (inner >> 6);
    int chunk = inner & 63;
    int row  = (chunk << 3) + line;
    size_t ibase = (size_t)img*N2 + (size_t)row*NN;
    BREV_DECL;
    cplx v[8], w[8];
#pragma unroll
    for (int r=0;r<8;r++){
        v[r] = h2c(d_field[ibase + j + 64*r]);
        w[r] = h2c(d_field[ibase + j + 32 + 64*r]);
    }
    fft512_dual<true,false>(v, w, S + line*RSTRIDE, S + SOFF + line*RSTRIDE, j, TW);

    float acc[10];
#pragma unroll
    for (int q=0;q<10;q++) acc[q] = 0.f;
#pragma unroll
    for (int i=0;i<8;i++){
        float2 f = c2f(v[i]);
        float I = f.x*f.x + f.y*f.y;
        int cl = d_cls[row*NN + j + 64*brev[i]];
#pragma unroll
        for (int q=0;q<10;q++) if (cl==q) acc[q] += I;
        f = c2f(w[i]);
        I = f.x*f.x + f.y*f.y;
        cl = d_cls[row*NN + j + 32 + 64*brev[i]];
#pragma unroll
        for (int q=0;q<10;q++) if (cl==q) acc[q] += I;
    }
#pragma unroll
    for (int q=0;q<10;q++){
#pragma unroll
        for (int o=16;o>0;o>>=1)
            acc[q] += __shfl_xor_sync(0xffffffffu, acc[q], o);
    }
    if (j == 0){
#pragma unroll
        for (int q=0;q<10;q++) WP[line][q] = acc[q];
    }
    __syncthreads();
    if (t < 10){
        float s = 0.f;
#pragma unroll
        for (int q=0;q<8;q++) s += WP[q][t];
        d_part[(img*64 + chunk)*10 + t] = s;
    }
}

// ---------------- mega kernel: software-pipelined pass dispatch ----------------
__global__ void __launch_bounds__(256,4) mega(int i, int gmin,
                                              const float* __restrict__ xamp,
                                              const float* __restrict__ pn){
    __shared__ __half2 S[2*SOFF];     // double-buffered exchange (~37.4KB)
    __shared__ float2 TW[TWSZ];       // skewed fp32 twiddle table
    __shared__ float WP[8][10];
    int t = threadIdx.x;
    TW[SK(t)] = d_tw[t]; TW[SK(t+256)] = d_tw[t+256];
    __syncthreads();                  // TW visible to ALL warps

    int slice = blockIdx.x / BPS;
    int inner = blockIdx.x - slice * BPS;
    int g = gmin + slice;
    int p = i - g;
    int img0 = g * GSIZE;

    switch (p){
        case 0: body_p1 (S, TW, xamp, pn, inner, img0); break;
        case 1: body_col(S, TW, d_Hb,  inner, img0); break;
        case 2: body_mid(S, TW, 1,     inner, img0); break;
        case 3: body_col(S, TW, d_Hb,  inner, img0); break;
        case 4: body_mid(S, TW, 2,     inner, img0); break;
        case 5: body_col(S, TW, d_Hb2, inner, img0); break;   // fused last two props
        default: body_p7(S, TW, WP,    inner, img0); break;
    }
}

// final: sum over 9 modes x 64 chunks, /9, scores [16,10]
__global__ void redB(float* __restrict__ out){
    __shared__ float sh[64];
    int t = threadIdx.x;
    int b = blockIdx.x / 10, c = blockIdx.x % 10;
    float s = 0.f;
#pragma unroll
    for (int m=0;m<9;m++)
        s += d_part[(((m*16+b) << 6) + t)*10 + c];
    sh[t] = s; __syncthreads();
    for (int w=32; w>0; w>>=1){ if (t < w) sh[t] += sh[t+w]; __syncthreads(); }
    if (t==0) out[blockIdx.x] = sh[0] * (1.0f/9.0f);
}

// ---------------- launch ----------------
extern "C" void kernel_launch(void* const* d_in, const int* in_sizes, int n_in,
                              void* d_out, int out_size){
    const float* x_amp  = (const float*)d_in[0];
    const float* pnoise = (const float*)d_in[1];
    const float* amp    = (const float*)d_in[2];
    const float* phs    = (const float*)d_in[3];
    const float* mask   = (const float*)d_in[4];
    float* out = (float*)d_out;

    k_init<<<512, 512>>>(amp, phs, mask);

    // pipelined schedule: launch i runs pass (i-g) of group g for all valid g;
    // GSIZE=12 keeps the 7-slice in-flight window (~84MB) L2-resident.
    for (int i = 0; i < NG + 6; i++){
        int gmin = (i > 6) ? (i - 6) : 0;
        int gmax = (i < NG-1) ? i : (NG-1);
        int ns = gmax - gmin + 1;
        mega<<<ns*BPS, 256>>>(i, gmin, x_amp, pnoise);
    }
    redB<<<160, 64>>>(out);
}